// round 15
// baseline (speedup 1.0000x reference)
#include <cuda_runtime.h>
#include <cuda_fp16.h>
#include <math.h>
#include <stdint.h>

// Problem constants
constexpr int cB   = 128;
constexpr int cT   = 256;
constexpr int cC   = 384;
constexpr int cH   = 6;
constexpr int cHS  = 64;
constexpr int cDFF = 1536;
constexpr int cBT  = cB * cT;          // 32768
constexpr int cQKV = 3 * cC;           // 1152

// ---------------- scratch (static device globals; no allocation) -------------
__device__ __half g_h   [cBT * cC];
__device__ __half g_wqkv[cQKV * cC];        // [N=1152][K=384] fp16
__device__ __half g_wo  [cC * cC];
__device__ __half g_w1  [cDFF * cC];
__device__ __half g_w2  [cC * cDFF];
__device__ __half g_qkv [cBT * cQKV];       // fp16 now
__device__ __half g_attn[cBT * cC];
__device__ float  g_x1  [cBT * cC];
__device__ __half g_ff1 [cBT * cDFF];

// ---------------- helpers ----------------------------------------------------
__device__ __forceinline__ void mma_f16(float c[4], const uint32_t a[4], const uint32_t b[2]) {
    asm volatile(
        "mma.sync.aligned.m16n8k16.row.col.f32.f16.f16.f32 "
        "{%0,%1,%2,%3}, {%4,%5,%6,%7}, {%8,%9}, {%0,%1,%2,%3};\n"
        : "+f"(c[0]), "+f"(c[1]), "+f"(c[2]), "+f"(c[3])
        : "r"(a[0]), "r"(a[1]), "r"(a[2]), "r"(a[3]), "r"(b[0]), "r"(b[1]));
}

__device__ __forceinline__ void ldsm_x4(uint32_t r[4], uint32_t addr) {
    asm volatile("ldmatrix.sync.aligned.m8n8.x4.shared.b16 {%0,%1,%2,%3}, [%4];"
        : "=r"(r[0]), "=r"(r[1]), "=r"(r[2]), "=r"(r[3]) : "r"(addr));
}
__device__ __forceinline__ void ldsm_x4_trans(uint32_t r[4], uint32_t addr) {
    asm volatile("ldmatrix.sync.aligned.m8n8.x4.trans.shared.b16 {%0,%1,%2,%3}, [%4];"
        : "=r"(r[0]), "=r"(r[1]), "=r"(r[2]), "=r"(r[3]) : "r"(addr));
}

__device__ __forceinline__ void cpasync16(uint32_t dst_smem, const void* src) {
    asm volatile("cp.async.ca.shared.global [%0], [%1], 16;\n"
                 :: "r"(dst_smem), "l"(src));
}
__device__ __forceinline__ void cpasync_commit() {
    asm volatile("cp.async.commit_group;\n");
}
__device__ __forceinline__ void cpasync_wait0() {
    asm volatile("cp.async.wait_group 0;\n");
}
__device__ __forceinline__ uint32_t smem_addr_u32(const void* p) {
    uint32_t a;
    asm("{ .reg .u64 t; cvta.to.shared.u64 t, %1; cvt.u32.u64 %0, t; }"
        : "=r"(a) : "l"(p));
    return a;
}

// ---------------- LayerNorm: fp16 output --------------------------------------
__global__ void ln_kernel(const float* __restrict__ x,
                          const float* __restrict__ g,
                          const float* __restrict__ b,
                          __half* __restrict__ out)
{
    int row = blockIdx.x;
    const float* xr = x + (size_t)row * cC;
    __half* orow    = out + (size_t)row * cC;
    int t = threadIdx.x;

    float v0 = xr[t], v1 = xr[t + 128], v2 = xr[t + 256];
    float s  = v0 + v1 + v2;

    __shared__ float sh[4];
    __shared__ float sh2[4];
    #pragma unroll
    for (int o = 16; o; o >>= 1) s += __shfl_xor_sync(0xffffffffu, s, o);
    if ((t & 31) == 0) sh[t >> 5] = s;
    __syncthreads();
    float mu = (sh[0] + sh[1] + sh[2] + sh[3]) * (1.0f / cC);

    float d0 = v0 - mu, d1 = v1 - mu, d2 = v2 - mu;
    float sq = d0 * d0 + d1 * d1 + d2 * d2;
    #pragma unroll
    for (int o = 16; o; o >>= 1) sq += __shfl_xor_sync(0xffffffffu, sq, o);
    if ((t & 31) == 0) sh2[t >> 5] = sq;
    __syncthreads();
    float var = (sh2[0] + sh2[1] + sh2[2] + sh2[3]) * (1.0f / cC);
    float r = rsqrtf(var + 1e-5f);

    orow[t]       = __float2half_rn(d0 * r * g[t]       + b[t]);
    orow[t + 128] = __float2half_rn(d1 * r * g[t + 128] + b[t + 128]);
    orow[t + 256] = __float2half_rn(d2 * r * g[t + 256] + b[t + 256]);
}

// ---------------- pack Wq|Wk|Wv -> [N=1152][K=384] fp16 ------------------------
__global__ void pack_qkv_t(const float* __restrict__ Wq,
                           const float* __restrict__ Wk,
                           const float* __restrict__ Wv,
                           __half* __restrict__ Wt)
{
    int idx = blockIdx.x * 256 + threadIdx.x;
    if (idx >= cQKV * cC) return;
    int n = idx / cC;
    int k = idx % cC;
    int which = n / cC;
    int rem   = n % cC;
    int head  = rem / cHS;
    int d     = rem % cHS;
    const float* W = (which == 0) ? Wq : (which == 1) ? Wk : Wv;
    Wt[idx] = __float2half_rn(W[((size_t)head * cC + k) * cHS + d]);
}

// ---------------- transpose+convert Wo/W1/W2 into [N][K] fp16 ------------------
__global__ void transpose_weights(const float* __restrict__ Wo,
                                  const float* __restrict__ W1,
                                  const float* __restrict__ W2,
                                  __half* __restrict__ wo_t,
                                  __half* __restrict__ w1_t,
                                  __half* __restrict__ w2_t)
{
    int i = blockIdx.x * 256 + threadIdx.x;
    if (i < cC * cC) {
        int n = i / cC, k = i % cC;
        wo_t[i] = __float2half_rn(Wo[(size_t)k * cC + n]);
    }
    if (i < cDFF * cC) {
        int n = i / cC, k = i % cC;
        w1_t[i] = __float2half_rn(W1[(size_t)k * cDFF + n]);
    }
    if (i < cC * cDFF) {
        int n = i / cDFF, k = i % cDFF;
        w2_t[i] = __float2half_rn(W2[(size_t)k * cC + n]);
    }
}

// ---------------- fp16 GEMM, 128x128x64 tiles, 8 warps (R11 geometry) ----------
constexpr int ROW_B    = 144;
constexpr int A_BYTES  = 128 * ROW_B;                 // 18432
constexpr int STAGE_B  = 2 * A_BYTES;                 // 36864
constexpr int GEMM_SMEM_BYTES = 2 * STAGE_B;          // 73728

__global__ __launch_bounds__(256, 2) void gemm_f16(
    const __half* __restrict__ A, const __half* __restrict__ Bt,
    const float* __restrict__ bias, const float* __restrict__ resid,
    float* __restrict__ CoutF, __half* __restrict__ CoutH,
    int M, int N, int K, int relu)
{
    extern __shared__ char sm8[];
    uint32_t sb = smem_addr_u32(sm8);

    int tid = threadIdx.x;
    int bx = blockIdx.x, by = blockIdx.y;
    int m0 = by * 128, n0 = bx * 128;

    const __half* Ab = A  + (size_t)m0 * K;
    const __half* Bb = Bt + (size_t)n0 * K;

    int wid = tid >> 5, lane = tid & 31;
    int wm = (wid & 1) * 64;
    int wn = (wid >> 1) * 32;
    int g  = lane >> 2;
    int tg = lane & 3;

    int q = lane >> 3;
    int rowoff = (q & 1) * 8 + (lane & 7);
    int coloff = (q >> 1) * 16;
    uint32_t aQ[4];
    #pragma unroll
    for (int i = 0; i < 4; i++)
        aQ[i] = sb + (wm + i * 16 + rowoff) * ROW_B + coloff;

    int r  = tid >> 1;
    int hh = tid & 1;

    float acc[4][4][4];
    #pragma unroll
    for (int i = 0; i < 4; i++)
        #pragma unroll
        for (int j = 0; j < 4; j++)
            #pragma unroll
            for (int u = 0; u < 4; u++) acc[i][j][u] = 0.0f;

    int niter = K >> 6;

    auto load_chunk = [&](int c, int stg) {
        uint32_t ad = sb + stg * STAGE_B + r * ROW_B + hh * 64;
        uint32_t bd = ad + A_BYTES;
        const __half* as = Ab + (size_t)r * K + c * 64 + hh * 32;
        const __half* bs = Bb + (size_t)r * K + c * 64 + hh * 32;
        #pragma unroll
        for (int u = 0; u < 4; u++) {
            cpasync16(ad + u * 16, as + u * 8);
            cpasync16(bd + u * 16, bs + u * 8);
        }
        cpasync_commit();
    };

    load_chunk(0, 0);

    int buf = 0;
    for (int it = 0; it < niter; it++) {
        cpasync_wait0();
        __syncthreads();

        if (it + 1 < niter) load_chunk(it + 1, buf ^ 1);

        uint32_t aoff = (uint32_t)(buf * STAGE_B);
        const char* Bp = sm8 + buf * STAGE_B + A_BYTES;

        #pragma unroll
        for (int kk = 0; kk < 4; kk++) {
            uint32_t af[4][4], bf[4][2];
            #pragma unroll
            for (int i = 0; i < 4; i++)
                ldsm_x4(af[i], aQ[i] + aoff + kk * 32);
            #pragma unroll
            for (int j = 0; j < 4; j++) {
                const char* brow = Bp + (wn + j * 8 + g) * ROW_B + kk * 32 + tg * 4;
                bf[j][0] = *(const uint32_t*)(brow);
                bf[j][1] = *(const uint32_t*)(brow + 16);
            }
            #pragma unroll
            for (int i = 0; i < 4; i++)
                #pragma unroll
                for (int j = 0; j < 4; j++)
                    mma_f16(acc[i][j], af[i], bf[j]);
        }
        __syncthreads();
        buf ^= 1;
    }

    #pragma unroll
    for (int i = 0; i < 4; i++) {
        #pragma unroll
        for (int j = 0; j < 4; j++) {
            int row = m0 + wm + i * 16 + g;
            int col = n0 + wn + j * 8 + tg * 2;
            float2 bv = make_float2(0.f, 0.f);
            if (bias) bv = *(const float2*)(bias + col);

            float2 v0 = make_float2(acc[i][j][0] + bv.x, acc[i][j][1] + bv.y);
            float2 v1 = make_float2(acc[i][j][2] + bv.x, acc[i][j][3] + bv.y);
            if (relu) {
                v0.x = fmaxf(v0.x, 0.f); v0.y = fmaxf(v0.y, 0.f);
                v1.x = fmaxf(v1.x, 0.f); v1.y = fmaxf(v1.y, 0.f);
            }
            size_t o0 = (size_t)row * N + col;
            size_t o1 = (size_t)(row + 8) * N + col;
            if (resid) {
                float2 r0 = *(const float2*)(resid + o0);
                float2 r1 = *(const float2*)(resid + o1);
                v0.x += r0.x; v0.y += r0.y;
                v1.x += r1.x; v1.y += r1.y;
            }
            if (CoutH) {
                *(__half2*)(CoutH + o0) = __floats2half2_rn(v0.x, v0.y);
                *(__half2*)(CoutH + o1) = __floats2half2_rn(v1.x, v1.y);
            } else {
                *(float2*)(CoutF + o0) = v0;
                *(float2*)(CoutF + o1) = v1;
            }
        }
    }
}

// ---------------- flash attention, fp16 mma (k16) ------------------------------
// Smem: Ks[64][72]h, Vs[64][72]h, Ss[64][68]f, Ps[64][72]h, rows[192]f
constexpr int OFF_KS = 0;
constexpr int OFF_VS = 9216;
constexpr int OFF_SS = 18432;
constexpr int OFF_PS = 35840;
constexpr int OFF_RW = 45056;
constexpr int ATTN_SMEM_BYTES = 45824;

__global__ __launch_bounds__(128) void attn_flash(
    const __half* __restrict__ qkv, __half* __restrict__ out)
{
    extern __shared__ char smA[];
    __half* Ks = (__half*)(smA + OFF_KS);
    __half* Vs = (__half*)(smA + OFF_VS);
    float*  Ss = (float*)(smA + OFF_SS);
    __half* Ps = (__half*)(smA + OFF_PS);
    float* row_m = (float*)(smA + OFF_RW);
    float* row_l = row_m + 64;
    float* row_c = row_l + 64;
    uint32_t sbVs = smem_addr_u32(Vs);

    int qt = blockIdx.x, head = blockIdx.y, b = blockIdx.z;
    int tid = threadIdx.x;
    int wid = tid >> 5, lane = tid & 31;
    int g = lane >> 2, tg = lane & 3;
    int wm = wid * 16;

    // Q frags straight from gmem, scaled by 1/8 (exact in fp16)
    uint32_t qf[4][4];
    {
        const __half* q0 = qkv + (size_t)(b * cT + qt * 64 + wm + g) * cQKV + head * cHS;
        const __half* q1 = q0 + 8 * (size_t)cQKV;
        __half2 s2 = __float2half2_rn(0.125f);
        #pragma unroll
        for (int kk = 0; kk < 4; kk++) {
            __half2 v;
            v = __hmul2(*(const __half2*)(q0 + kk * 16 + 2 * tg), s2);
            qf[kk][0] = *(uint32_t*)&v;
            v = __hmul2(*(const __half2*)(q1 + kk * 16 + 2 * tg), s2);
            qf[kk][1] = *(uint32_t*)&v;
            v = __hmul2(*(const __half2*)(q0 + kk * 16 + 8 + 2 * tg), s2);
            qf[kk][2] = *(uint32_t*)&v;
            v = __hmul2(*(const __half2*)(q1 + kk * 16 + 8 + 2 * tg), s2);
            qf[kk][3] = *(uint32_t*)&v;
        }
    }
    if (lane < 16) { row_m[wm + lane] = -1e30f; row_l[wm + lane] = 0.0f; }

    float o[8][4];
    #pragma unroll
    for (int j = 0; j < 8; j++)
        #pragma unroll
        for (int u = 0; u < 4; u++) o[j][u] = 0.0f;

    const __half* kgbase = qkv + (size_t)(b * cT) * cQKV + cC + head * cHS;

    int ntiles = qt + 1;
    for (int ti = 0; ti < ntiles; ti++) {
        int s0 = ti * 64;

        // load K and V tiles (fp16, 128B rows -> stride 144B)
        {
            int r = tid >> 1, c0h = (tid & 1) * 32;
            const __half* ksrc = kgbase + (size_t)(s0 + r) * cQKV + c0h;
            const __half* vsrc = ksrc + cC;
            uint4* kd = (uint4*)((char*)Ks + r * 144 + c0h * 2);
            uint4* vd = (uint4*)((char*)Vs + r * 144 + c0h * 2);
            #pragma unroll
            for (int u = 0; u < 4; u++) {
                kd[u] = ((const uint4*)ksrc)[u];
                vd[u] = ((const uint4*)vsrc)[u];
            }
        }
        __syncthreads();

        // S = Q @ K^T  (fp16 mma, k16)
        #pragma unroll
        for (int jn = 0; jn < 8; jn++) {
            float sc[4] = {0.f, 0.f, 0.f, 0.f};
            const __half* krow = Ks + (jn * 8 + g) * 72;
            #pragma unroll
            for (int kk = 0; kk < 4; kk++) {
                uint32_t kb[2];
                kb[0] = *(const uint32_t*)(krow + kk * 16 + 2 * tg);
                kb[1] = *(const uint32_t*)(krow + kk * 16 + 8 + 2 * tg);
                mma_f16(sc, qf[kk], kb);
            }
            Ss[(wm + g    ) * 68 + jn * 8 + 2 * tg    ] = sc[0];
            Ss[(wm + g    ) * 68 + jn * 8 + 2 * tg + 1] = sc[1];
            Ss[(wm + g + 8) * 68 + jn * 8 + 2 * tg    ] = sc[2];
            Ss[(wm + g + 8) * 68 + jn * 8 + 2 * tg + 1] = sc[3];
        }
        __syncwarp();

        // online softmax; write P as fp16
        {
            int rloc = wm + (lane >> 1);
            int half = lane & 1;
            float* srow = Ss + rloc * 68 + half * 32;
            __half* prow = Ps + rloc * 72 + half * 32;
            int ig = qt * 64 + rloc;
            int jbase = s0 + half * 32;
            bool diag = (ti == qt);

            float mx = -1e30f;
            if (diag) {
                #pragma unroll
                for (int c = 0; c < 32; c++) {
                    float v = (jbase + c <= ig) ? srow[c] : -1e30f;
                    srow[c] = v;
                    mx = fmaxf(mx, v);
                }
            } else {
                #pragma unroll
                for (int c = 0; c < 32; c++) mx = fmaxf(mx, srow[c]);
            }
            mx = fmaxf(mx, __shfl_xor_sync(0xffffffffu, mx, 1));

            float om = row_m[rloc];
            float nm = fmaxf(om, mx);
            float corr = __expf(om - nm);

            float se = 0.0f;
            #pragma unroll
            for (int c = 0; c < 32; c += 2) {
                float e0 = __expf(srow[c    ] - nm);
                float e1 = __expf(srow[c + 1] - nm);
                *(__half2*)(prow + c) = __floats2half2_rn(e0, e1);
                se += e0 + e1;
            }
            se += __shfl_xor_sync(0xffffffffu, se, 1);

            if (half == 0) {
                row_m[rloc] = nm;
                row_l[rloc] = row_l[rloc] * corr + se;
                row_c[rloc] = corr;
            }
        }
        __syncwarp();

        // rescale O, then O += P @ V (fp16 mma; V frags via ldmatrix.trans)
        {
            float c0 = row_c[wm + g], c1 = row_c[wm + g + 8];
            #pragma unroll
            for (int j = 0; j < 8; j++) {
                o[j][0] *= c0; o[j][1] *= c0;
                o[j][2] *= c1; o[j][3] *= c1;
            }
        }
        #pragma unroll
        for (int kk = 0; kk < 4; kk++) {
            uint32_t pf[4];
            const __half* p0 = Ps + (wm + g) * 72 + kk * 16;
            const __half* p1 = p0 + 8 * 72;
            pf[0] = *(const uint32_t*)(p0 + 2 * tg);
            pf[1] = *(const uint32_t*)(p1 + 2 * tg);
            pf[2] = *(const uint32_t*)(p0 + 8 + 2 * tg);
            pf[3] = *(const uint32_t*)(p1 + 8 + 2 * tg);
            #pragma unroll
            for (int j2 = 0; j2 < 4; j2++) {
                uint32_t vb[4];
                uint32_t addr = sbVs + (kk * 16 + (lane & 15)) * 144
                              + (j2 * 16 + ((lane >> 4) * 8)) * 2;
                ldsm_x4_trans(vb, addr);
                uint32_t b0[2] = {vb[0], vb[1]};
                uint32_t b1[2] = {vb[2], vb[3]};
                mma_f16(o[2 * j2    ], pf, b0);
                mma_f16(o[2 * j2 + 1], pf, b1);
            }
        }
        __syncthreads();
    }

    // epilogue: divide by l, write fp16
    {
        float inv0 = 1.0f / row_l[wm + g];
        float inv1 = 1.0f / row_l[wm + g + 8];
        int r0 = b * cT + qt * 64 + wm + g;
        size_t base0 = (size_t)r0 * cC + head * cHS;
        size_t base1 = (size_t)(r0 + 8) * cC + head * cHS;
        #pragma unroll
        for (int j = 0; j < 8; j++) {
            int col = j * 8 + 2 * tg;
            *(__half2*)(out + base0 + col) = __floats2half2_rn(o[j][0] * inv0, o[j][1] * inv0);
            *(__half2*)(out + base1 + col) = __floats2half2_rn(o[j][2] * inv1, o[j][3] * inv1);
        }
    }
}

// ---------------- host orchestration ----------------------------------------
extern "C" void kernel_launch(void* const* d_in, const int* in_sizes, int n_in,
                              void* d_out, int out_size)
{
    const float* x   = (const float*)d_in[0];
    const float* Wq  = (const float*)d_in[1];
    const float* Wk  = (const float*)d_in[2];
    const float* Wv  = (const float*)d_in[3];
    const float* Wo  = (const float*)d_in[4];
    const float* bo  = (const float*)d_in[5];
    const float* W1  = (const float*)d_in[6];
    const float* b1  = (const float*)d_in[7];
    const float* W2  = (const float*)d_in[8];
    const float* b2  = (const float*)d_in[9];
    const float* g1  = (const float*)d_in[10];
    const float* be1 = (const float*)d_in[11];
    const float* g2  = (const float*)d_in[12];
    const float* be2 = (const float*)d_in[13];
    float* out = (float*)d_out;

    __half *p_h, *p_wqkv, *p_wo, *p_w1, *p_w2, *p_qkv, *p_attn, *p_ff1;
    float *p_x1;
    cudaGetSymbolAddress((void**)&p_h,    g_h);
    cudaGetSymbolAddress((void**)&p_wqkv, g_wqkv);
    cudaGetSymbolAddress((void**)&p_wo,   g_wo);
    cudaGetSymbolAddress((void**)&p_w1,   g_w1);
    cudaGetSymbolAddress((void**)&p_w2,   g_w2);
    cudaGetSymbolAddress((void**)&p_qkv,  g_qkv);
    cudaGetSymbolAddress((void**)&p_attn, g_attn);
    cudaGetSymbolAddress((void**)&p_x1,   g_x1);
    cudaGetSymbolAddress((void**)&p_ff1,  g_ff1);

    cudaFuncSetAttribute(attn_flash,
        cudaFuncAttributeMaxDynamicSharedMemorySize, ATTN_SMEM_BYTES);
    cudaFuncSetAttribute(gemm_f16,
        cudaFuncAttributeMaxDynamicSharedMemorySize, GEMM_SMEM_BYTES);

    // 1. h = LN(x, g1, be1)  [fp16]
    ln_kernel<<<cBT, 128>>>(x, g1, be1, p_h);

    // 2. pack+convert Wqkv transposed [1152][384] fp16
    pack_qkv_t<<<(cQKV * cC + 255) / 256, 256>>>(Wq, Wk, Wv, p_wqkv);

    // 3. transpose+convert Wo/W1/W2 fp16
    transpose_weights<<<(cDFF * cC + 255) / 256, 256>>>(Wo, W1, W2, p_wo, p_w1, p_w2);

    // 4. qkv = h @ Wqkv^T  (BT x 1152, fp16 out)   <- profiled launch
    {
        dim3 grid(cQKV / 128, cBT / 128);
        gemm_f16<<<grid, 256, GEMM_SMEM_BYTES>>>(p_h, p_wqkv, nullptr, nullptr,
                                                 nullptr, p_qkv, cBT, cQKV, cC, 0);
    }

    // 5. flash attention -> g_attn (fp16)
    {
        dim3 grid(cT / 64, cH, cB);
        attn_flash<<<grid, 128, ATTN_SMEM_BYTES>>>(p_qkv, p_attn);
    }

    // 6. x1 = x + attn @ Wo + bo   (fp32 out)
    {
        dim3 grid(cC / 128, cBT / 128);
        gemm_f16<<<grid, 256, GEMM_SMEM_BYTES>>>(p_attn, p_wo, bo, x,
                                                 p_x1, nullptr, cBT, cC, cC, 0);
    }

    // 7. h2 = LN(x1, g2, be2)  [fp16]
    ln_kernel<<<cBT, 128>>>(p_x1, g2, be2, p_h);

    // 8. ff1 = relu(h2 @ W1 + b1)  [fp16 out]
    {
        dim3 grid(cDFF / 128, cBT / 128);
        gemm_f16<<<grid, 256, GEMM_SMEM_BYTES>>>(p_h, p_w1, b1, nullptr,
                                                 nullptr, p_ff1, cBT, cDFF, cC, 1);
    }

    // 9. out = x1 + ff1 @ W2 + b2  (fp32 out)
    {
        dim3 grid(cC / 128, cBT / 128);
        gemm_f16<<<grid, 256, GEMM_SMEM_BYTES>>>(p_ff1, p_w2, b2, p_x1,
                                                 out, nullptr, cBT, cC, cDFF, 0);
    }
}

// round 16
// speedup vs baseline: 1.0010x; 1.0010x over previous
#include <cuda_runtime.h>
#include <cuda_fp16.h>
#include <math.h>
#include <stdint.h>

// Problem constants
constexpr int cB   = 128;
constexpr int cT   = 256;
constexpr int cC   = 384;
constexpr int cH   = 6;
constexpr int cHS  = 64;
constexpr int cDFF = 1536;
constexpr int cBT  = cB * cT;          // 32768
constexpr int cQKV = 3 * cC;           // 1152

// ---------------- scratch (static device globals; no allocation) -------------
__device__ __half g_h   [cBT * cC];
__device__ __half g_wqkv[cQKV * cC];        // [N=1152][K=384] fp16
__device__ __half g_wo  [cC * cC];
__device__ __half g_w1  [cDFF * cC];
__device__ __half g_w2  [cC * cDFF];
__device__ __half g_qkv [cBT * cQKV];       // fp16 now
__device__ __half g_attn[cBT * cC];
__device__ float  g_x1  [cBT * cC];
__device__ __half g_ff1 [cBT * cDFF];

// ---------------- helpers ----------------------------------------------------
__device__ __forceinline__ void mma_f16(float c[4], const uint32_t a[4], const uint32_t b[2]) {
    asm volatile(
        "mma.sync.aligned.m16n8k16.row.col.f32.f16.f16.f32 "
        "{%0,%1,%2,%3}, {%4,%5,%6,%7}, {%8,%9}, {%0,%1,%2,%3};\n"
        : "+f"(c[0]), "+f"(c[1]), "+f"(c[2]), "+f"(c[3])
        : "r"(a[0]), "r"(a[1]), "r"(a[2]), "r"(a[3]), "r"(b[0]), "r"(b[1]));
}

__device__ __forceinline__ void ldsm_x4(uint32_t r[4], uint32_t addr) {
    asm volatile("ldmatrix.sync.aligned.m8n8.x4.shared.b16 {%0,%1,%2,%3}, [%4];"
        : "=r"(r[0]), "=r"(r[1]), "=r"(r[2]), "=r"(r[3]) : "r"(addr));
}
__device__ __forceinline__ void ldsm_x4_trans(uint32_t r[4], uint32_t addr) {
    asm volatile("ldmatrix.sync.aligned.m8n8.x4.trans.shared.b16 {%0,%1,%2,%3}, [%4];"
        : "=r"(r[0]), "=r"(r[1]), "=r"(r[2]), "=r"(r[3]) : "r"(addr));
}

__device__ __forceinline__ void cpasync16(uint32_t dst_smem, const void* src) {
    asm volatile("cp.async.ca.shared.global [%0], [%1], 16;\n"
                 :: "r"(dst_smem), "l"(src));
}
__device__ __forceinline__ void cpasync_commit() {
    asm volatile("cp.async.commit_group;\n");
}
__device__ __forceinline__ void cpasync_wait0() {
    asm volatile("cp.async.wait_group 0;\n");
}
__device__ __forceinline__ uint32_t smem_addr_u32(const void* p) {
    uint32_t a;
    asm("{ .reg .u64 t; cvta.to.shared.u64 t, %1; cvt.u32.u64 %0, t; }"
        : "=r"(a) : "l"(p));
    return a;
}

// ---------------- LayerNorm: fp16 output --------------------------------------
__global__ void ln_kernel(const float* __restrict__ x,
                          const float* __restrict__ g,
                          const float* __restrict__ b,
                          __half* __restrict__ out)
{
    int row = blockIdx.x;
    const float* xr = x + (size_t)row * cC;
    __half* orow    = out + (size_t)row * cC;
    int t = threadIdx.x;

    float v0 = xr[t], v1 = xr[t + 128], v2 = xr[t + 256];
    float s  = v0 + v1 + v2;

    __shared__ float sh[4];
    __shared__ float sh2[4];
    #pragma unroll
    for (int o = 16; o; o >>= 1) s += __shfl_xor_sync(0xffffffffu, s, o);
    if ((t & 31) == 0) sh[t >> 5] = s;
    __syncthreads();
    float mu = (sh[0] + sh[1] + sh[2] + sh[3]) * (1.0f / cC);

    float d0 = v0 - mu, d1 = v1 - mu, d2 = v2 - mu;
    float sq = d0 * d0 + d1 * d1 + d2 * d2;
    #pragma unroll
    for (int o = 16; o; o >>= 1) sq += __shfl_xor_sync(0xffffffffu, sq, o);
    if ((t & 31) == 0) sh2[t >> 5] = sq;
    __syncthreads();
    float var = (sh2[0] + sh2[1] + sh2[2] + sh2[3]) * (1.0f / cC);
    float r = rsqrtf(var + 1e-5f);

    orow[t]       = __float2half_rn(d0 * r * g[t]       + b[t]);
    orow[t + 128] = __float2half_rn(d1 * r * g[t + 128] + b[t + 128]);
    orow[t + 256] = __float2half_rn(d2 * r * g[t + 256] + b[t + 256]);
}

// ---------------- pack Wq|Wk|Wv -> [N=1152][K=384] fp16 ------------------------
__global__ void pack_qkv_t(const float* __restrict__ Wq,
                           const float* __restrict__ Wk,
                           const float* __restrict__ Wv,
                           __half* __restrict__ Wt)
{
    int idx = blockIdx.x * 256 + threadIdx.x;
    if (idx >= cQKV * cC) return;
    int n = idx / cC;
    int k = idx % cC;
    int which = n / cC;
    int rem   = n % cC;
    int head  = rem / cHS;
    int d     = rem % cHS;
    const float* W = (which == 0) ? Wq : (which == 1) ? Wk : Wv;
    Wt[idx] = __float2half_rn(W[((size_t)head * cC + k) * cHS + d]);
}

// ---------------- transpose+convert Wo/W1/W2 into [N][K] fp16 ------------------
__global__ void transpose_weights(const float* __restrict__ Wo,
                                  const float* __restrict__ W1,
                                  const float* __restrict__ W2,
                                  __half* __restrict__ wo_t,
                                  __half* __restrict__ w1_t,
                                  __half* __restrict__ w2_t)
{
    int i = blockIdx.x * 256 + threadIdx.x;
    if (i < cC * cC) {
        int n = i / cC, k = i % cC;
        wo_t[i] = __float2half_rn(Wo[(size_t)k * cC + n]);
    }
    if (i < cDFF * cC) {
        int n = i / cC, k = i % cC;
        w1_t[i] = __float2half_rn(W1[(size_t)k * cDFF + n]);
    }
    if (i < cC * cDFF) {
        int n = i / cDFF, k = i % cDFF;
        w2_t[i] = __float2half_rn(W2[(size_t)k * cC + n]);
    }
}

// ---------------- fp16 GEMM, 128x128x64 tiles, 8 warps (R11 geometry) ----------
constexpr int ROW_B    = 144;
constexpr int A_BYTES  = 128 * ROW_B;                 // 18432
constexpr int STAGE_B  = 2 * A_BYTES;                 // 36864
constexpr int GEMM_SMEM_BYTES = 2 * STAGE_B;          // 73728

__global__ __launch_bounds__(256, 2) void gemm_f16(
    const __half* __restrict__ A, const __half* __restrict__ Bt,
    const float* __restrict__ bias, const float* __restrict__ resid,
    float* __restrict__ CoutF, __half* __restrict__ CoutH,
    int M, int N, int K, int relu)
{
    extern __shared__ char sm8[];
    uint32_t sb = smem_addr_u32(sm8);

    int tid = threadIdx.x;
    int bx = blockIdx.x, by = blockIdx.y;
    int m0 = by * 128, n0 = bx * 128;

    const __half* Ab = A  + (size_t)m0 * K;
    const __half* Bb = Bt + (size_t)n0 * K;

    int wid = tid >> 5, lane = tid & 31;
    int wm = (wid & 1) * 64;
    int wn = (wid >> 1) * 32;
    int g  = lane >> 2;
    int tg = lane & 3;

    int q = lane >> 3;
    int rowoff = (q & 1) * 8 + (lane & 7);
    int coloff = (q >> 1) * 16;
    uint32_t aQ[4];
    #pragma unroll
    for (int i = 0; i < 4; i++)
        aQ[i] = sb + (wm + i * 16 + rowoff) * ROW_B + coloff;

    int r  = tid >> 1;
    int hh = tid & 1;

    float acc[4][4][4];
    #pragma unroll
    for (int i = 0; i < 4; i++)
        #pragma unroll
        for (int j = 0; j < 4; j++)
            #pragma unroll
            for (int u = 0; u < 4; u++) acc[i][j][u] = 0.0f;

    int niter = K >> 6;

    auto load_chunk = [&](int c, int stg) {
        uint32_t ad = sb + stg * STAGE_B + r * ROW_B + hh * 64;
        uint32_t bd = ad + A_BYTES;
        const __half* as = Ab + (size_t)r * K + c * 64 + hh * 32;
        const __half* bs = Bb + (size_t)r * K + c * 64 + hh * 32;
        #pragma unroll
        for (int u = 0; u < 4; u++) {
            cpasync16(ad + u * 16, as + u * 8);
            cpasync16(bd + u * 16, bs + u * 8);
        }
        cpasync_commit();
    };

    load_chunk(0, 0);

    int buf = 0;
    for (int it = 0; it < niter; it++) {
        cpasync_wait0();
        __syncthreads();

        if (it + 1 < niter) load_chunk(it + 1, buf ^ 1);

        uint32_t aoff = (uint32_t)(buf * STAGE_B);
        const char* Bp = sm8 + buf * STAGE_B + A_BYTES;

        #pragma unroll
        for (int kk = 0; kk < 4; kk++) {
            uint32_t af[4][4], bf[4][2];
            #pragma unroll
            for (int i = 0; i < 4; i++)
                ldsm_x4(af[i], aQ[i] + aoff + kk * 32);
            #pragma unroll
            for (int j = 0; j < 4; j++) {
                const char* brow = Bp + (wn + j * 8 + g) * ROW_B + kk * 32 + tg * 4;
                bf[j][0] = *(const uint32_t*)(brow);
                bf[j][1] = *(const uint32_t*)(brow + 16);
            }
            #pragma unroll
            for (int i = 0; i < 4; i++)
                #pragma unroll
                for (int j = 0; j < 4; j++)
                    mma_f16(acc[i][j], af[i], bf[j]);
        }
        __syncthreads();
        buf ^= 1;
    }

    #pragma unroll
    for (int i = 0; i < 4; i++) {
        #pragma unroll
        for (int j = 0; j < 4; j++) {
            int row = m0 + wm + i * 16 + g;
            int col = n0 + wn + j * 8 + tg * 2;
            float2 bv = make_float2(0.f, 0.f);
            if (bias) bv = *(const float2*)(bias + col);

            float2 v0 = make_float2(acc[i][j][0] + bv.x, acc[i][j][1] + bv.y);
            float2 v1 = make_float2(acc[i][j][2] + bv.x, acc[i][j][3] + bv.y);
            if (relu) {
                v0.x = fmaxf(v0.x, 0.f); v0.y = fmaxf(v0.y, 0.f);
                v1.x = fmaxf(v1.x, 0.f); v1.y = fmaxf(v1.y, 0.f);
            }
            size_t o0 = (size_t)row * N + col;
            size_t o1 = (size_t)(row + 8) * N + col;
            if (resid) {
                float2 r0 = *(const float2*)(resid + o0);
                float2 r1 = *(const float2*)(resid + o1);
                v0.x += r0.x; v0.y += r0.y;
                v1.x += r1.x; v1.y += r1.y;
            }
            if (CoutH) {
                *(__half2*)(CoutH + o0) = __floats2half2_rn(v0.x, v0.y);
                *(__half2*)(CoutH + o1) = __floats2half2_rn(v1.x, v1.y);
            } else {
                *(float2*)(CoutF + o0) = v0;
                *(float2*)(CoutF + o1) = v1;
            }
        }
    }
}

// ---------------- flash attention, fp16 mma (k16) ------------------------------
// Smem: Ks[64][72]h, Vs[64][72]h, Ss[64][68]f, Ps[64][72]h, rows[192]f
constexpr int OFF_KS = 0;
constexpr int OFF_VS = 9216;
constexpr int OFF_SS = 18432;
constexpr int OFF_PS = 35840;
constexpr int OFF_RW = 45056;
constexpr int ATTN_SMEM_BYTES = 45824;

__global__ __launch_bounds__(128) void attn_flash(
    const __half* __restrict__ qkv, __half* __restrict__ out)
{
    extern __shared__ char smA[];
    __half* Ks = (__half*)(smA + OFF_KS);
    __half* Vs = (__half*)(smA + OFF_VS);
    float*  Ss = (float*)(smA + OFF_SS);
    __half* Ps = (__half*)(smA + OFF_PS);
    float* row_m = (float*)(smA + OFF_RW);
    float* row_l = row_m + 64;
    float* row_c = row_l + 64;
    uint32_t sbVs = smem_addr_u32(Vs);

    int qt = blockIdx.x, head = blockIdx.y, b = blockIdx.z;
    int tid = threadIdx.x;
    int wid = tid >> 5, lane = tid & 31;
    int g = lane >> 2, tg = lane & 3;
    int wm = wid * 16;

    // Q frags straight from gmem, scaled by 1/8 (exact in fp16)
    uint32_t qf[4][4];
    {
        const __half* q0 = qkv + (size_t)(b * cT + qt * 64 + wm + g) * cQKV + head * cHS;
        const __half* q1 = q0 + 8 * (size_t)cQKV;
        __half2 s2 = __float2half2_rn(0.125f);
        #pragma unroll
        for (int kk = 0; kk < 4; kk++) {
            __half2 v;
            v = __hmul2(*(const __half2*)(q0 + kk * 16 + 2 * tg), s2);
            qf[kk][0] = *(uint32_t*)&v;
            v = __hmul2(*(const __half2*)(q1 + kk * 16 + 2 * tg), s2);
            qf[kk][1] = *(uint32_t*)&v;
            v = __hmul2(*(const __half2*)(q0 + kk * 16 + 8 + 2 * tg), s2);
            qf[kk][2] = *(uint32_t*)&v;
            v = __hmul2(*(const __half2*)(q1 + kk * 16 + 8 + 2 * tg), s2);
            qf[kk][3] = *(uint32_t*)&v;
        }
    }
    if (lane < 16) { row_m[wm + lane] = -1e30f; row_l[wm + lane] = 0.0f; }

    float o[8][4];
    #pragma unroll
    for (int j = 0; j < 8; j++)
        #pragma unroll
        for (int u = 0; u < 4; u++) o[j][u] = 0.0f;

    const __half* kgbase = qkv + (size_t)(b * cT) * cQKV + cC + head * cHS;

    int ntiles = qt + 1;
    for (int ti = 0; ti < ntiles; ti++) {
        int s0 = ti * 64;

        // load K and V tiles (fp16, 128B rows -> stride 144B)
        {
            int r = tid >> 1, c0h = (tid & 1) * 32;
            const __half* ksrc = kgbase + (size_t)(s0 + r) * cQKV + c0h;
            const __half* vsrc = ksrc + cC;
            uint4* kd = (uint4*)((char*)Ks + r * 144 + c0h * 2);
            uint4* vd = (uint4*)((char*)Vs + r * 144 + c0h * 2);
            #pragma unroll
            for (int u = 0; u < 4; u++) {
                kd[u] = ((const uint4*)ksrc)[u];
                vd[u] = ((const uint4*)vsrc)[u];
            }
        }
        __syncthreads();

        // S = Q @ K^T  (fp16 mma, k16)
        #pragma unroll
        for (int jn = 0; jn < 8; jn++) {
            float sc[4] = {0.f, 0.f, 0.f, 0.f};
            const __half* krow = Ks + (jn * 8 + g) * 72;
            #pragma unroll
            for (int kk = 0; kk < 4; kk++) {
                uint32_t kb[2];
                kb[0] = *(const uint32_t*)(krow + kk * 16 + 2 * tg);
                kb[1] = *(const uint32_t*)(krow + kk * 16 + 8 + 2 * tg);
                mma_f16(sc, qf[kk], kb);
            }
            Ss[(wm + g    ) * 68 + jn * 8 + 2 * tg    ] = sc[0];
            Ss[(wm + g    ) * 68 + jn * 8 + 2 * tg + 1] = sc[1];
            Ss[(wm + g + 8) * 68 + jn * 8 + 2 * tg    ] = sc[2];
            Ss[(wm + g + 8) * 68 + jn * 8 + 2 * tg + 1] = sc[3];
        }
        __syncwarp();

        // online softmax; write P as fp16
        {
            int rloc = wm + (lane >> 1);
            int half = lane & 1;
            float* srow = Ss + rloc * 68 + half * 32;
            __half* prow = Ps + rloc * 72 + half * 32;
            int ig = qt * 64 + rloc;
            int jbase = s0 + half * 32;
            bool diag = (ti == qt);

            float mx = -1e30f;
            if (diag) {
                #pragma unroll
                for (int c = 0; c < 32; c++) {
                    float v = (jbase + c <= ig) ? srow[c] : -1e30f;
                    srow[c] = v;
                    mx = fmaxf(mx, v);
                }
            } else {
                #pragma unroll
                for (int c = 0; c < 32; c++) mx = fmaxf(mx, srow[c]);
            }
            mx = fmaxf(mx, __shfl_xor_sync(0xffffffffu, mx, 1));

            float om = row_m[rloc];
            float nm = fmaxf(om, mx);
            float corr = __expf(om - nm);

            float se = 0.0f;
            #pragma unroll
            for (int c = 0; c < 32; c += 2) {
                float e0 = __expf(srow[c    ] - nm);
                float e1 = __expf(srow[c + 1] - nm);
                *(__half2*)(prow + c) = __floats2half2_rn(e0, e1);
                se += e0 + e1;
            }
            se += __shfl_xor_sync(0xffffffffu, se, 1);

            if (half == 0) {
                row_m[rloc] = nm;
                row_l[rloc] = row_l[rloc] * corr + se;
                row_c[rloc] = corr;
            }
        }
        __syncwarp();

        // rescale O, then O += P @ V (fp16 mma; V frags via ldmatrix.trans)
        {
            float c0 = row_c[wm + g], c1 = row_c[wm + g + 8];
            #pragma unroll
            for (int j = 0; j < 8; j++) {
                o[j][0] *= c0; o[j][1] *= c0;
                o[j][2] *= c1; o[j][3] *= c1;
            }
        }
        #pragma unroll
        for (int kk = 0; kk < 4; kk++) {
            uint32_t pf[4];
            const __half* p0 = Ps + (wm + g) * 72 + kk * 16;
            const __half* p1 = p0 + 8 * 72;
            pf[0] = *(const uint32_t*)(p0 + 2 * tg);
            pf[1] = *(const uint32_t*)(p1 + 2 * tg);
            pf[2] = *(const uint32_t*)(p0 + 8 + 2 * tg);
            pf[3] = *(const uint32_t*)(p1 + 8 + 2 * tg);
            #pragma unroll
            for (int j2 = 0; j2 < 4; j2++) {
                uint32_t vb[4];
                uint32_t addr = sbVs + (kk * 16 + (lane & 15)) * 144
                              + (j2 * 16 + ((lane >> 4) * 8)) * 2;
                ldsm_x4_trans(vb, addr);
                uint32_t b0[2] = {vb[0], vb[1]};
                uint32_t b1[2] = {vb[2], vb[3]};
                mma_f16(o[2 * j2    ], pf, b0);
                mma_f16(o[2 * j2 + 1], pf, b1);
            }
        }
        __syncthreads();
    }

    // epilogue: divide by l, write fp16
    {
        float inv0 = 1.0f / row_l[wm + g];
        float inv1 = 1.0f / row_l[wm + g + 8];
        int r0 = b * cT + qt * 64 + wm + g;
        size_t base0 = (size_t)r0 * cC + head * cHS;
        size_t base1 = (size_t)(r0 + 8) * cC + head * cHS;
        #pragma unroll
        for (int j = 0; j < 8; j++) {
            int col = j * 8 + 2 * tg;
            *(__half2*)(out + base0 + col) = __floats2half2_rn(o[j][0] * inv0, o[j][1] * inv0);
            *(__half2*)(out + base1 + col) = __floats2half2_rn(o[j][2] * inv1, o[j][3] * inv1);
        }
    }
}

// ---------------- host orchestration ----------------------------------------
extern "C" void kernel_launch(void* const* d_in, const int* in_sizes, int n_in,
                              void* d_out, int out_size)
{
    const float* x   = (const float*)d_in[0];
    const float* Wq  = (const float*)d_in[1];
    const float* Wk  = (const float*)d_in[2];
    const float* Wv  = (const float*)d_in[3];
    const float* Wo  = (const float*)d_in[4];
    const float* bo  = (const float*)d_in[5];
    const float* W1  = (const float*)d_in[6];
    const float* b1  = (const float*)d_in[7];
    const float* W2  = (const float*)d_in[8];
    const float* b2  = (const float*)d_in[9];
    const float* g1  = (const float*)d_in[10];
    const float* be1 = (const float*)d_in[11];
    const float* g2  = (const float*)d_in[12];
    const float* be2 = (const float*)d_in[13];
    float* out = (float*)d_out;

    __half *p_h, *p_wqkv, *p_wo, *p_w1, *p_w2, *p_qkv, *p_attn, *p_ff1;
    float *p_x1;
    cudaGetSymbolAddress((void**)&p_h,    g_h);
    cudaGetSymbolAddress((void**)&p_wqkv, g_wqkv);
    cudaGetSymbolAddress((void**)&p_wo,   g_wo);
    cudaGetSymbolAddress((void**)&p_w1,   g_w1);
    cudaGetSymbolAddress((void**)&p_w2,   g_w2);
    cudaGetSymbolAddress((void**)&p_qkv,  g_qkv);
    cudaGetSymbolAddress((void**)&p_attn, g_attn);
    cudaGetSymbolAddress((void**)&p_x1,   g_x1);
    cudaGetSymbolAddress((void**)&p_ff1,  g_ff1);

    cudaFuncSetAttribute(attn_flash,
        cudaFuncAttributeMaxDynamicSharedMemorySize, ATTN_SMEM_BYTES);
    cudaFuncSetAttribute(gemm_f16,
        cudaFuncAttributeMaxDynamicSharedMemorySize, GEMM_SMEM_BYTES);

    // 1. h = LN(x, g1, be1)  [fp16]
    ln_kernel<<<cBT, 128>>>(x, g1, be1, p_h);

    // 2. pack+convert Wqkv transposed [1152][384] fp16
    pack_qkv_t<<<(cQKV * cC + 255) / 256, 256>>>(Wq, Wk, Wv, p_wqkv);

    // 3. transpose+convert Wo/W1/W2 fp16
    transpose_weights<<<(cDFF * cC + 255) / 256, 256>>>(Wo, W1, W2, p_wo, p_w1, p_w2);

    // 4. qkv = h @ Wqkv^T  (BT x 1152, fp16 out)   <- profiled launch
    {
        dim3 grid(cQKV / 128, cBT / 128);
        gemm_f16<<<grid, 256, GEMM_SMEM_BYTES>>>(p_h, p_wqkv, nullptr, nullptr,
                                                 nullptr, p_qkv, cBT, cQKV, cC, 0);
    }

    // 5. flash attention -> g_attn (fp16)
    {
        dim3 grid(cT / 64, cH, cB);
        attn_flash<<<grid, 128, ATTN_SMEM_BYTES>>>(p_qkv, p_attn);
    }

    // 6. x1 = x + attn @ Wo + bo   (fp32 out)
    {
        dim3 grid(cC / 128, cBT / 128);
        gemm_f16<<<grid, 256, GEMM_SMEM_BYTES>>>(p_attn, p_wo, bo, x,
                                                 p_x1, nullptr, cBT, cC, cC, 0);
    }

    // 7. h2 = LN(x1, g2, be2)  [fp16]
    ln_kernel<<<cBT, 128>>>(p_x1, g2, be2, p_h);

    // 8. ff1 = relu(h2 @ W1 + b1)  [fp16 out]
    {
        dim3 grid(cDFF / 128, cBT / 128);
        gemm_f16<<<grid, 256, GEMM_SMEM_BYTES>>>(p_h, p_w1, b1, nullptr,
                                                 nullptr, p_ff1, cBT, cDFF, cC, 1);
    }

    // 9. out = x1 + ff1 @ W2 + b2  (fp32 out)
    {
        dim3 grid(cC / 128, cBT / 128);
        gemm_f16<<<grid, 256, GEMM_SMEM_BYTES>>>(p_ff1, p_w2, b2, p_x1,
                                                 out, nullptr, cBT, cC, cDFF, 0);
    }
}